// round 15
// baseline (speedup 1.0000x reference)
#include <cuda_runtime.h>
#include <math.h>

// Problem constants
#define BB 8
#define NS 1024
#define CC 384
#define HH 6
#define DD 64
#define SPAN 384
#define TWOSPAN 768

// ---------------- device scratch (no allocations allowed) ----------------
__device__ float g_q[BB * NS * CC];      // (B,N,C) q projection
__device__ float g_k[BB * NS * CC];      // (B,N,C) k projection
__device__ float g_v[BB * NS * CC];      // (B,N,C) v projection
__device__ float g_att[BB * NS * CC];    // (B,N,C) attention output (pre-Wo)
__device__ float g_posk[TWOSPAN * CC];   // (768,C) pos_k projection
__device__ float g_posq[TWOSPAN * CC];   // (768,C) pos_q projection
__device__ float g_Qp[(size_t)BB * HH * NS * TWOSPAN]; // (B*H, N, 768)
__device__ float g_Kp[(size_t)BB * HH * NS * TWOSPAN]; // (B*H, N, 768)

// ---------------- plain NN GEMM with bias: C = A(MxK) @ B(KxN) + bias ----------------
// Tiles: 64x64, BK=16, 256 threads, 4x4 per thread.
__global__ void __launch_bounds__(256) gemm_nn_bias(
    const float* __restrict__ A, const float* __restrict__ Bm,
    const float* __restrict__ bias, float* __restrict__ Cm,
    int M, int Ncol, int K)
{
    __shared__ float As[64][20];   // padded
    __shared__ float Bs[16][68];   // padded

    int tid = threadIdx.x;
    int tx = tid & 15, ty = tid >> 4;
    int m0 = blockIdx.y * 64, n0 = blockIdx.x * 64;

    float acc[4][4];
#pragma unroll
    for (int i = 0; i < 4; i++)
#pragma unroll
        for (int j = 0; j < 4; j++) acc[i][j] = 0.f;

    int ar = tid >> 2, ak = (tid & 3) << 2;   // As load: row ar, 4 floats at ak
    int bk = tid >> 4, bc = (tid & 15) << 2;  // Bs load: row bk, 4 floats at bc

    for (int k0 = 0; k0 < K; k0 += 16) {
        float4 a4 = *(const float4*)(A + (size_t)(m0 + ar) * K + k0 + ak);
        As[ar][ak + 0] = a4.x; As[ar][ak + 1] = a4.y;
        As[ar][ak + 2] = a4.z; As[ar][ak + 3] = a4.w;
        float4 b4 = *(const float4*)(Bm + (size_t)(k0 + bk) * Ncol + n0 + bc);
        *(float4*)&Bs[bk][bc] = b4;
        __syncthreads();

#pragma unroll
        for (int kk = 0; kk < 16; kk += 4) {
            float av[4][4];
#pragma unroll
            for (int ii = 0; ii < 4; ii++) {
                float4 t = *(float4*)&As[ty * 4 + ii][kk];
                av[ii][0] = t.x; av[ii][1] = t.y; av[ii][2] = t.z; av[ii][3] = t.w;
            }
            float bv[4][4];
#pragma unroll
            for (int t = 0; t < 4; t++) {
                float4 u = *(float4*)&Bs[kk + t][tx * 4];
                bv[t][0] = u.x; bv[t][1] = u.y; bv[t][2] = u.z; bv[t][3] = u.w;
            }
#pragma unroll
            for (int ii = 0; ii < 4; ii++)
#pragma unroll
                for (int jj = 0; jj < 4; jj++)
#pragma unroll
                    for (int t = 0; t < 4; t++)
                        acc[ii][jj] += av[ii][t] * bv[t][jj];
        }
        __syncthreads();
    }

    float4 bb = *(const float4*)(bias + n0 + tx * 4);
#pragma unroll
    for (int ii = 0; ii < 4; ii++) {
        float4 o;
        o.x = acc[ii][0] + bb.x; o.y = acc[ii][1] + bb.y;
        o.z = acc[ii][2] + bb.z; o.w = acc[ii][3] + bb.w;
        *(float4*)(Cm + (size_t)(m0 + ty * 4 + ii) * Ncol + n0 + tx * 4) = o;
    }
}

// ---------------- Qp / Kp:  Qp[bh,i,p] = q[b,h,i,:] . pos_k[h,p,:]  (NT, K=64) ----------------
// grid: (768/64, 1024/64, B*H*2)   z = bh*2 + which (0=Qp from q/pos_k, 1=Kp from k/pos_q)
__global__ void __launch_bounds__(256) qpkp_kernel()
{
    __shared__ float aS[64][68];
    __shared__ float bS[64][68];

    int z = blockIdx.z;
    int which = z & 1;
    int bh = z >> 1;
    int b = bh / HH, h = bh % HH;

    const float* Abase = (which ? g_k : g_q) + (size_t)b * NS * CC + h * DD;
    const float* Pbase = (which ? g_posq : g_posk) + h * DD;
    float* Out = (which ? g_Kp : g_Qp) + (size_t)bh * NS * TWOSPAN;

    int i0 = blockIdx.y * 64, p0 = blockIdx.x * 64;
    int tid = threadIdx.x, tx = tid & 15, ty = tid >> 4;

    int r = tid >> 2, c4 = (tid & 3) << 4;
#pragma unroll
    for (int t = 0; t < 4; t++) {
        *(float4*)&aS[r][c4 + t * 4] =
            *(const float4*)(Abase + (size_t)(i0 + r) * CC + c4 + t * 4);
        *(float4*)&bS[r][c4 + t * 4] =
            *(const float4*)(Pbase + (size_t)(p0 + r) * CC + c4 + t * 4);
    }
    __syncthreads();

    float acc[4][4];
#pragma unroll
    for (int i = 0; i < 4; i++)
#pragma unroll
        for (int j = 0; j < 4; j++) acc[i][j] = 0.f;

#pragma unroll
    for (int dk = 0; dk < 64; dk += 4) {
        float av[4][4], bv[4][4];
#pragma unroll
        for (int ii = 0; ii < 4; ii++) {
            float4 t = *(float4*)&aS[ty * 4 + ii][dk];
            av[ii][0] = t.x; av[ii][1] = t.y; av[ii][2] = t.z; av[ii][3] = t.w;
        }
#pragma unroll
        for (int jj = 0; jj < 4; jj++) {
            float4 u = *(float4*)&bS[tx * 4 + jj][dk];
            bv[jj][0] = u.x; bv[jj][1] = u.y; bv[jj][2] = u.z; bv[jj][3] = u.w;
        }
#pragma unroll
        for (int ii = 0; ii < 4; ii++)
#pragma unroll
            for (int jj = 0; jj < 4; jj++)
#pragma unroll
                for (int t = 0; t < 4; t++)
                    acc[ii][jj] += av[ii][t] * bv[jj][t];
    }

#pragma unroll
    for (int ii = 0; ii < 4; ii++) {
        float4 o = {acc[ii][0], acc[ii][1], acc[ii][2], acc[ii][3]};
        *(float4*)(Out + (size_t)(i0 + ty * 4 + ii) * TWOSPAN + p0 + tx * 4) = o;
    }
}

// ---------------- fused flash attention with relative-position gathers ----------------
// grid: (N/64, B*H), 256 threads, dynamic smem.
// S[i,j] = ( q_i.k_j + Qp[i, c(i,j)] + Kp[j, c(i,j)] ) / sqrt(192),  c = clamp(i-j+384, 0, 767)
__global__ void __launch_bounds__(256) attn_kernel()
{
    extern __shared__ float sm[];
    float* qS  = sm;              // 64*68
    float* kS  = qS + 64 * 68;    // 64*68
    float* vS  = kS + 64 * 68;    // 64*68
    float* pS  = vS + 64 * 68;    // 64*68
    float* KpS = pS + 64 * 68;    // 64*128

    int bh = blockIdx.y;
    int b = bh / HH, h = bh % HH;
    int i0 = blockIdx.x * 64;
    int tid = threadIdx.x, tx = tid & 15, ty = tid >> 4;

    const float* qBase = g_q + (size_t)b * NS * CC + h * DD;
    const float* kBase = g_k + (size_t)b * NS * CC + h * DD;
    const float* vBase = g_v + (size_t)b * NS * CC + h * DD;
    const float* QpB = g_Qp + (size_t)bh * NS * TWOSPAN;
    const float* KpB = g_Kp + (size_t)bh * NS * TWOSPAN;

    // load q tile once
    {
        int r = tid >> 2, c4 = (tid & 3) << 4;
#pragma unroll
        for (int t = 0; t < 4; t++)
            *(float4*)&qS[r * 68 + c4 + t * 4] =
                *(const float4*)(qBase + (size_t)(i0 + r) * CC + c4 + t * 4);
    }

    float m[4], l[4], O[4][4];
#pragma unroll
    for (int ii = 0; ii < 4; ii++) {
        m[ii] = -1e30f; l[ii] = 0.f;
#pragma unroll
        for (int dd = 0; dd < 4; dd++) O[ii][dd] = 0.f;
    }
    const float inv_scale = rsqrtf((float)(DD * 3));

    for (int kt = 0; kt < NS / 64; kt++) {
        int j0 = kt * 64;

        // load k tile
        {
            int r = tid >> 2, c4 = (tid & 3) << 4;
#pragma unroll
            for (int t = 0; t < 4; t++)
                *(float4*)&kS[r * 68 + c4 + t * 4] =
                    *(const float4*)(kBase + (size_t)(j0 + r) * CC + c4 + t * 4);
        }
        // stage Kp band: KpS[jl][x] = Kp[j0+jl, clamp(i0-j0+321 + x)]   (x = il - jl + 63)
        {
            int base = i0 - j0 + 321;
            for (int e = tid; e < 64 * 128; e += 256) {
                int jl = e >> 7, x = e & 127;
                int p = base + x;
                p = p < 0 ? 0 : (p > 767 ? 767 : p);
                KpS[jl * 128 + x] = KpB[(size_t)(j0 + jl) * TWOSPAN + p];
            }
        }
        __syncthreads();

        // S = q.k^T
        float s[4][4];
#pragma unroll
        for (int i = 0; i < 4; i++)
#pragma unroll
            for (int j = 0; j < 4; j++) s[i][j] = 0.f;

#pragma unroll
        for (int dk = 0; dk < 64; dk += 4) {
            float av[4][4], bv[4][4];
#pragma unroll
            for (int ii = 0; ii < 4; ii++) {
                float4 t = *(float4*)&qS[(ty * 4 + ii) * 68 + dk];
                av[ii][0] = t.x; av[ii][1] = t.y; av[ii][2] = t.z; av[ii][3] = t.w;
            }
#pragma unroll
            for (int jj = 0; jj < 4; jj++) {
                float4 u = *(float4*)&kS[(tx * 4 + jj) * 68 + dk];
                bv[jj][0] = u.x; bv[jj][1] = u.y; bv[jj][2] = u.z; bv[jj][3] = u.w;
            }
#pragma unroll
            for (int ii = 0; ii < 4; ii++)
#pragma unroll
                for (int jj = 0; jj < 4; jj++)
#pragma unroll
                    for (int t = 0; t < 4; t++)
                        s[ii][jj] += av[ii][t] * bv[jj][t];
        }

        // add positional gathers, scale, row max
        float tmax[4];
#pragma unroll
        for (int ii = 0; ii < 4; ii++) {
            int il = ty * 4 + ii, i = i0 + il;
            const float* Qprow = QpB + (size_t)i * TWOSPAN;
            float rowm = -1e30f;
#pragma unroll
            for (int jj = 0; jj < 4; jj++) {
                int jl = tx * 4 + jj, j = j0 + jl;
                int p = i - j + SPAN;
                p = p < 0 ? 0 : (p > 767 ? 767 : p);
                float val = (s[ii][jj] + Qprow[p] + KpS[jl * 128 + il - jl + 63]) * inv_scale;
                s[ii][jj] = val;
                rowm = fmaxf(rowm, val);
            }
#pragma unroll
            for (int o = 8; o >= 1; o >>= 1)
                rowm = fmaxf(rowm, __shfl_xor_sync(0xffffffffu, rowm, o, 16));
            tmax[ii] = rowm;
        }

        // online softmax update
#pragma unroll
        for (int ii = 0; ii < 4; ii++) {
            float newm = fmaxf(m[ii], tmax[ii]);
            float fac = __expf(m[ii] - newm);
            m[ii] = newm;
            float rsum = 0.f;
#pragma unroll
            for (int jj = 0; jj < 4; jj++) {
                float pv = __expf(s[ii][jj] - newm);
                s[ii][jj] = pv;
                rsum += pv;
            }
#pragma unroll
            for (int o = 8; o >= 1; o >>= 1)
                rsum += __shfl_xor_sync(0xffffffffu, rsum, o, 16);
            l[ii] = l[ii] * fac + rsum;
#pragma unroll
            for (int dd = 0; dd < 4; dd++) O[ii][dd] *= fac;
        }

        // write P to smem, load v tile
#pragma unroll
        for (int ii = 0; ii < 4; ii++) {
            float4 p4 = {s[ii][0], s[ii][1], s[ii][2], s[ii][3]};
            *(float4*)&pS[(ty * 4 + ii) * 68 + tx * 4] = p4;
        }
        {
            int r = tid >> 2, c4 = (tid & 3) << 4;
#pragma unroll
            for (int t = 0; t < 4; t++)
                *(float4*)&vS[r * 68 + c4 + t * 4] =
                    *(const float4*)(vBase + (size_t)(j0 + r) * CC + c4 + t * 4);
        }
        __syncthreads();

        // O += P @ V
#pragma unroll
        for (int jl4 = 0; jl4 < 64; jl4 += 4) {
            float pv[4][4], vv[4][4];
#pragma unroll
            for (int ii = 0; ii < 4; ii++) {
                float4 t = *(float4*)&pS[(ty * 4 + ii) * 68 + jl4];
                pv[ii][0] = t.x; pv[ii][1] = t.y; pv[ii][2] = t.z; pv[ii][3] = t.w;
            }
#pragma unroll
            for (int t = 0; t < 4; t++) {
                float4 u = *(float4*)&vS[(jl4 + t) * 68 + tx * 4];
                vv[t][0] = u.x; vv[t][1] = u.y; vv[t][2] = u.z; vv[t][3] = u.w;
            }
#pragma unroll
            for (int ii = 0; ii < 4; ii++)
#pragma unroll
                for (int dd = 0; dd < 4; dd++)
#pragma unroll
                    for (int t = 0; t < 4; t++)
                        O[ii][dd] += pv[ii][t] * vv[t][dd];
        }
        __syncthreads();
    }

    // epilogue: normalize and store to (B,N,C) layout
#pragma unroll
    for (int ii = 0; ii < 4; ii++) {
        float inv_l = 1.0f / l[ii];
        float4 o = {O[ii][0] * inv_l, O[ii][1] * inv_l, O[ii][2] * inv_l, O[ii][3] * inv_l};
        *(float4*)(g_att + (size_t)(b * NS + i0 + ty * 4 + ii) * CC + h * DD + tx * 4) = o;
    }
}

// ---------------- host launcher ----------------
extern "C" void kernel_launch(void* const* d_in, const int* in_sizes, int n_in,
                              void* d_out, int out_size)
{
    (void)in_sizes; (void)n_in; (void)out_size;
    const float* x   = (const float*)d_in[0];
    // d_in[1] = relative_pos (int32) — index is analytic (i-j), unused
    const float* rel = (const float*)d_in[2];
    const float* Wq  = (const float*)d_in[3];  const float* bq  = (const float*)d_in[4];
    const float* Wk  = (const float*)d_in[5];  const float* bk  = (const float*)d_in[6];
    const float* Wv  = (const float*)d_in[7];  const float* bv  = (const float*)d_in[8];
    const float* Wpk = (const float*)d_in[9];  const float* bpk = (const float*)d_in[10];
    const float* Wpq = (const float*)d_in[11]; const float* bpq = (const float*)d_in[12];
    const float* Wo  = (const float*)d_in[13]; const float* bo  = (const float*)d_in[14];
    float* out = (float*)d_out;

    float *q, *k, *v, *att, *pk, *pq;
    cudaGetSymbolAddress((void**)&q,   g_q);
    cudaGetSymbolAddress((void**)&k,   g_k);
    cudaGetSymbolAddress((void**)&v,   g_v);
    cudaGetSymbolAddress((void**)&att, g_att);
    cudaGetSymbolAddress((void**)&pk,  g_posk);
    cudaGetSymbolAddress((void**)&pq,  g_posq);

    const int ATTN_SMEM = (4 * 64 * 68 + 64 * 128) * 4; // 102400 bytes
    cudaFuncSetAttribute(attn_kernel, cudaFuncAttributeMaxDynamicSharedMemorySize, ATTN_SMEM);

    dim3 blk(256);
    // content + positional projections
    gemm_nn_bias<<<dim3(CC / 64, (BB * NS) / 64), blk>>>(x, Wq, bq, q, BB * NS, CC, CC);
    gemm_nn_bias<<<dim3(CC / 64, (BB * NS) / 64), blk>>>(x, Wk, bk, k, BB * NS, CC, CC);
    gemm_nn_bias<<<dim3(CC / 64, (BB * NS) / 64), blk>>>(x, Wv, bv, v, BB * NS, CC, CC);
    gemm_nn_bias<<<dim3(CC / 64, TWOSPAN / 64), blk>>>(rel, Wpk, bpk, pk, TWOSPAN, CC, CC);
    gemm_nn_bias<<<dim3(CC / 64, TWOSPAN / 64), blk>>>(rel, Wpq, bpq, pq, TWOSPAN, CC, CC);
    // Qp = q @ pos_k^T, Kp = k @ pos_q^T  (per b,h)
    qpkp_kernel<<<dim3(TWOSPAN / 64, NS / 64, BB * HH * 2), blk>>>();
    // fused attention with relative-position gathers
    attn_kernel<<<dim3(NS / 64, BB * HH), blk, ATTN_SMEM>>>();
    // output projection
    gemm_nn_bias<<<dim3(CC / 64, (BB * NS) / 64), blk>>>(att, Wo, bo, out, BB * NS, CC, CC);
}

// round 16
// speedup vs baseline: 3.1037x; 3.1037x over previous
#include <cuda_runtime.h>
#include <stdint.h>
#include <math.h>

// Problem constants
#define BB 8
#define NS 1024
#define CC 384
#define HH 6
#define DD 64
#define SPAN 384
#define TWOSPAN 768

// ---------------- device scratch ----------------
__device__ float g_q[BB * NS * CC];
__device__ float g_k[BB * NS * CC];
__device__ float g_v[BB * NS * CC];
__device__ float g_att[BB * NS * CC];
__device__ float g_posk[TWOSPAN * CC];
__device__ float g_posq[TWOSPAN * CC];
__device__ float g_Qp[(size_t)BB * HH * NS * TWOSPAN];
__device__ float g_Kp[(size_t)BB * HH * NS * TWOSPAN];

// ---------------- tf32 helpers ----------------
__device__ __forceinline__ uint32_t f2tf(float x) {
    uint32_t r;
    asm("cvt.rna.tf32.f32 %0, %1;" : "=r"(r) : "f"(x));
    return r;
}

// D = A(16x8,row) * B(8x8,col) + D, tf32 inputs, f32 accum
__device__ __forceinline__ void mma8(float* c, const uint32_t* a, const uint32_t* b) {
    asm volatile(
        "mma.sync.aligned.m16n8k8.row.col.f32.tf32.tf32.f32 "
        "{%0,%1,%2,%3},{%4,%5,%6,%7},{%8,%9},{%0,%1,%2,%3};"
        : "+f"(c[0]), "+f"(c[1]), "+f"(c[2]), "+f"(c[3])
        : "r"(a[0]), "r"(a[1]), "r"(a[2]), "r"(a[3]), "r"(b[0]), "r"(b[1]));
}

// ---------------- projection GEMM (MMA): C = A(Mx384) @ W(384x384) + bias ----------------
// Block: 128x64, 256 threads, 8 warps (4m x 2n), warp tile 32x32.
// blockIdx.z selects one of up to 3 (W, bias, C) sets (same A).
__global__ void __launch_bounds__(256) proj_mma(
    const float* __restrict__ A, int M,
    const float* __restrict__ W0, const float* __restrict__ W1, const float* __restrict__ W2,
    const float* __restrict__ B0, const float* __restrict__ B1, const float* __restrict__ B2,
    float* __restrict__ C0, float* __restrict__ C1, float* __restrict__ C2)
{
    const float* W    = blockIdx.z == 0 ? W0 : (blockIdx.z == 1 ? W1 : W2);
    const float* bias = blockIdx.z == 0 ? B0 : (blockIdx.z == 1 ? B1 : B2);
    float*       C    = blockIdx.z == 0 ? C0 : (blockIdx.z == 1 ? C1 : C2);

    __shared__ uint32_t aS[128][36];  // (4g+t)%32 conflict-free
    __shared__ uint32_t wS[32][72];   // (8t+g)%32 conflict-free

    int tid = threadIdx.x, w = tid >> 5, lane = tid & 31, g = lane >> 2, tg = lane & 3;
    int wm = w >> 1, wn = w & 1;
    int m0 = blockIdx.y * 128, n0 = blockIdx.x * 64;

    float c[2][4][4];
#pragma unroll
    for (int mt = 0; mt < 2; mt++)
#pragma unroll
        for (int nt = 0; nt < 4; nt++)
#pragma unroll
            for (int r = 0; r < 4; r++) c[mt][nt][r] = 0.f;

    int ar = tid >> 1, ac = (tid & 1) << 4;
    int wr = tid >> 3, wc = (tid & 7) << 3;

    for (int k0 = 0; k0 < 384; k0 += 32) {
        const float* ap = A + (size_t)(m0 + ar) * 384 + k0 + ac;
#pragma unroll
        for (int t = 0; t < 4; t++) {
            float4 v4 = *(const float4*)(ap + t * 4);
            aS[ar][ac + t * 4 + 0] = f2tf(v4.x);
            aS[ar][ac + t * 4 + 1] = f2tf(v4.y);
            aS[ar][ac + t * 4 + 2] = f2tf(v4.z);
            aS[ar][ac + t * 4 + 3] = f2tf(v4.w);
        }
        const float* wp = W + (size_t)(k0 + wr) * 384 + n0 + wc;
#pragma unroll
        for (int t = 0; t < 2; t++) {
            float4 v4 = *(const float4*)(wp + t * 4);
            wS[wr][wc + t * 4 + 0] = f2tf(v4.x);
            wS[wr][wc + t * 4 + 1] = f2tf(v4.y);
            wS[wr][wc + t * 4 + 2] = f2tf(v4.z);
            wS[wr][wc + t * 4 + 3] = f2tf(v4.w);
        }
        __syncthreads();

#pragma unroll
        for (int ks = 0; ks < 4; ks++) {
            uint32_t bf[4][2];
#pragma unroll
            for (int nt = 0; nt < 4; nt++) {
                bf[nt][0] = wS[8 * ks + tg][32 * wn + 8 * nt + g];
                bf[nt][1] = wS[8 * ks + tg + 4][32 * wn + 8 * nt + g];
            }
#pragma unroll
            for (int mt = 0; mt < 2; mt++) {
                int r = 32 * wm + 16 * mt + g;
                uint32_t af[4];
                af[0] = aS[r][8 * ks + tg];
                af[1] = aS[r + 8][8 * ks + tg];
                af[2] = aS[r][8 * ks + tg + 4];
                af[3] = aS[r + 8][8 * ks + tg + 4];
#pragma unroll
                for (int nt = 0; nt < 4; nt++) mma8(c[mt][nt], af, bf[nt]);
            }
        }
        __syncthreads();
    }

#pragma unroll
    for (int mt = 0; mt < 2; mt++)
#pragma unroll
        for (int nt = 0; nt < 4; nt++) {
            int row = m0 + 32 * wm + 16 * mt + g;
            int col = n0 + 32 * wn + 8 * nt + 2 * tg;
            float bx = bias[col], by = bias[col + 1];
            float2 o1 = {c[mt][nt][0] + bx, c[mt][nt][1] + by};
            float2 o2 = {c[mt][nt][2] + bx, c[mt][nt][3] + by};
            *(float2*)(C + (size_t)row * 384 + col) = o1;
            *(float2*)(C + (size_t)(row + 8) * 384 + col) = o2;
        }
}

// ---------------- Qp/Kp batched NT GEMM (MMA), K=64 one-shot ----------------
// Block: 128(m) x 128(n), 8 warps (2m x 4n), warp tile 64x32.
// grid.z = bh*2 + which
__global__ void __launch_bounds__(256) qpkp_mma()
{
    extern __shared__ uint32_t sm_u[];
    uint32_t (*aS)[68] = (uint32_t(*)[68])sm_u;               // 128 x 68
    uint32_t (*bS)[68] = (uint32_t(*)[68])(sm_u + 128 * 68);  // 128 x 68

    int z = blockIdx.z, which = z & 1, bh = z >> 1;
    int b = bh / HH, h = bh % HH;
    const float* Ab = (which ? g_k : g_q) + (size_t)b * NS * CC + h * DD;
    const float* Pb = (which ? g_posq : g_posk) + h * DD;
    float* Out = (which ? g_Kp : g_Qp) + (size_t)bh * NS * TWOSPAN;
    int i0 = blockIdx.y * 128, p0 = blockIdx.x * 128;

    int tid = threadIdx.x, w = tid >> 5, lane = tid & 31, g = lane >> 2, tg = lane & 3;
    int wm = w >> 2, wn = w & 3;

    int r = tid >> 1, cb = (tid & 1) * 32;
#pragma unroll
    for (int t = 0; t < 8; t++) {
        float4 v4 = *(const float4*)(Ab + (size_t)(i0 + r) * CC + cb + t * 4);
        aS[r][cb + t * 4 + 0] = f2tf(v4.x);
        aS[r][cb + t * 4 + 1] = f2tf(v4.y);
        aS[r][cb + t * 4 + 2] = f2tf(v4.z);
        aS[r][cb + t * 4 + 3] = f2tf(v4.w);
        float4 u4 = *(const float4*)(Pb + (size_t)(p0 + r) * CC + cb + t * 4);
        bS[r][cb + t * 4 + 0] = f2tf(u4.x);
        bS[r][cb + t * 4 + 1] = f2tf(u4.y);
        bS[r][cb + t * 4 + 2] = f2tf(u4.z);
        bS[r][cb + t * 4 + 3] = f2tf(u4.w);
    }
    __syncthreads();

    float c[4][4][4];
#pragma unroll
    for (int mt = 0; mt < 4; mt++)
#pragma unroll
        for (int nt = 0; nt < 4; nt++)
#pragma unroll
            for (int q = 0; q < 4; q++) c[mt][nt][q] = 0.f;

#pragma unroll
    for (int ks = 0; ks < 8; ks++) {
        uint32_t bf[4][2], af[4][4];
#pragma unroll
        for (int nt = 0; nt < 4; nt++) {
            int pr = 32 * wn + 8 * nt + g;
            bf[nt][0] = bS[pr][8 * ks + tg];
            bf[nt][1] = bS[pr][8 * ks + tg + 4];
        }
#pragma unroll
        for (int mt = 0; mt < 4; mt++) {
            int rr = 64 * wm + 16 * mt + g;
            af[mt][0] = aS[rr][8 * ks + tg];
            af[mt][1] = aS[rr + 8][8 * ks + tg];
            af[mt][2] = aS[rr][8 * ks + tg + 4];
            af[mt][3] = aS[rr + 8][8 * ks + tg + 4];
        }
#pragma unroll
        for (int mt = 0; mt < 4; mt++)
#pragma unroll
            for (int nt = 0; nt < 4; nt++) mma8(c[mt][nt], af[mt], bf[nt]);
    }

#pragma unroll
    for (int mt = 0; mt < 4; mt++)
#pragma unroll
        for (int nt = 0; nt < 4; nt++) {
            int row = i0 + 64 * wm + 16 * mt + g;
            int col = p0 + 32 * wn + 8 * nt + 2 * tg;
            float2 o1 = {c[mt][nt][0], c[mt][nt][1]};
            float2 o2 = {c[mt][nt][2], c[mt][nt][3]};
            *(float2*)(Out + (size_t)row * TWOSPAN + col) = o1;
            *(float2*)(Out + (size_t)(row + 8) * TWOSPAN + col) = o2;
        }
}

// ---------------- fused flash attention (MMA) with relative-position gathers ----------------
// Block: 128 q-rows, 8 warps x 16 rows each, K/V tiles of 64.
__global__ void __launch_bounds__(256) attn_mma()
{
    extern __shared__ uint32_t sm_u[];
    uint32_t (*kS)[68] = (uint32_t(*)[68])sm_u;                          // 64 x 68
    uint32_t (*vS)[72] = (uint32_t(*)[72])(sm_u + 64 * 68);              // 64 x 72
    uint32_t (*pS)[68] = (uint32_t(*)[68])(sm_u + 64 * 68 + 64 * 72);    // 128 x 68

    int bh = blockIdx.y, b = bh / HH, h = bh % HH;
    int i0 = blockIdx.x * 128;
    int tid = threadIdx.x, w = tid >> 5, lane = tid & 31, g = lane >> 2, tg = lane & 3;
    int iw = i0 + 16 * w;
    int i1 = iw + g, i2 = i1 + 8;

    const float* qB = g_q + (size_t)b * NS * CC + h * DD;
    const float* kB = g_k + (size_t)b * NS * CC + h * DD;
    const float* vB = g_v + (size_t)b * NS * CC + h * DD;
    const float* QpB = g_Qp + (size_t)bh * NS * TWOSPAN;
    const float* KpB = g_Kp + (size_t)bh * NS * TWOSPAN;

    // Q fragments held in registers for the whole kernel
    uint32_t qf[8][4];
#pragma unroll
    for (int ks = 0; ks < 8; ks++) {
        qf[ks][0] = f2tf(qB[(size_t)i1 * CC + 8 * ks + tg]);
        qf[ks][1] = f2tf(qB[(size_t)i2 * CC + 8 * ks + tg]);
        qf[ks][2] = f2tf(qB[(size_t)i1 * CC + 8 * ks + tg + 4]);
        qf[ks][3] = f2tf(qB[(size_t)i2 * CC + 8 * ks + tg + 4]);
    }

    float o[8][4];
#pragma unroll
    for (int nt = 0; nt < 8; nt++)
#pragma unroll
        for (int q = 0; q < 4; q++) o[nt][q] = 0.f;
    float m1 = -1e30f, m2 = -1e30f, l1 = 0.f, l2 = 0.f;
    const float isc = rsqrtf((float)(DD * 3));

    int lr = tid >> 2, lc = (tid & 3) * 16;
    int pr1 = 16 * w + g, pr2 = pr1 + 8;

    for (int kt = 0; kt < NS / 64; kt++) {
        int j0 = kt * 64;

        // cooperative load of K/V tiles (tf32-converted)
#pragma unroll
        for (int t = 0; t < 4; t++) {
            float4 v4 = *(const float4*)(kB + (size_t)(j0 + lr) * CC + lc + t * 4);
            kS[lr][lc + t * 4 + 0] = f2tf(v4.x);
            kS[lr][lc + t * 4 + 1] = f2tf(v4.y);
            kS[lr][lc + t * 4 + 2] = f2tf(v4.z);
            kS[lr][lc + t * 4 + 3] = f2tf(v4.w);
            float4 u4 = *(const float4*)(vB + (size_t)(j0 + lr) * CC + lc + t * 4);
            vS[lr][lc + t * 4 + 0] = f2tf(u4.x);
            vS[lr][lc + t * 4 + 1] = f2tf(u4.y);
            vS[lr][lc + t * 4 + 2] = f2tf(u4.z);
            vS[lr][lc + t * 4 + 3] = f2tf(u4.w);
        }
        __syncthreads();

        // S = Q K^T
        float s[8][4];
#pragma unroll
        for (int nt = 0; nt < 8; nt++)
#pragma unroll
            for (int q = 0; q < 4; q++) s[nt][q] = 0.f;
#pragma unroll
        for (int ks = 0; ks < 8; ks++)
#pragma unroll
            for (int nt = 0; nt < 8; nt++) {
                uint32_t bf[2];
                bf[0] = kS[8 * nt + g][8 * ks + tg];
                bf[1] = kS[8 * nt + g][8 * ks + tg + 4];
                mma8(s[nt], qf[ks], bf);
            }

        // positional gathers + scale + row max
        float mx1 = -1e30f, mx2 = -1e30f;
#pragma unroll
        for (int nt = 0; nt < 8; nt++) {
            int j = j0 + 8 * nt + 2 * tg;
            int p10 = min(max(i1 - j + SPAN, 0), TWOSPAN - 1);
            int p11 = min(max(i1 - j - 1 + SPAN, 0), TWOSPAN - 1);
            int p20 = min(max(i2 - j + SPAN, 0), TWOSPAN - 1);
            int p21 = min(max(i2 - j - 1 + SPAN, 0), TWOSPAN - 1);
            s[nt][0] = (s[nt][0] + QpB[(size_t)i1 * TWOSPAN + p10] + KpB[(size_t)j * TWOSPAN + p10]) * isc;
            s[nt][1] = (s[nt][1] + QpB[(size_t)i1 * TWOSPAN + p11] + KpB[(size_t)(j + 1) * TWOSPAN + p11]) * isc;
            s[nt][2] = (s[nt][2] + QpB[(size_t)i2 * TWOSPAN + p20] + KpB[(size_t)j * TWOSPAN + p20]) * isc;
            s[nt][3] = (s[nt][3] + QpB[(size_t)i2 * TWOSPAN + p21] + KpB[(size_t)(j + 1) * TWOSPAN + p21]) * isc;
            mx1 = fmaxf(mx1, fmaxf(s[nt][0], s[nt][1]));
            mx2 = fmaxf(mx2, fmaxf(s[nt][2], s[nt][3]));
        }
        mx1 = fmaxf(mx1, __shfl_xor_sync(0xffffffffu, mx1, 1));
        mx1 = fmaxf(mx1, __shfl_xor_sync(0xffffffffu, mx1, 2));
        mx2 = fmaxf(mx2, __shfl_xor_sync(0xffffffffu, mx2, 1));
        mx2 = fmaxf(mx2, __shfl_xor_sync(0xffffffffu, mx2, 2));

        // online softmax update
        float nm1 = fmaxf(m1, mx1), nm2 = fmaxf(m2, mx2);
        float f1 = __expf(m1 - nm1), f2 = __expf(m2 - nm2);
        m1 = nm1; m2 = nm2;
        float rs1 = 0.f, rs2 = 0.f;
#pragma unroll
        for (int nt = 0; nt < 8; nt++) {
            s[nt][0] = __expf(s[nt][0] - nm1);
            s[nt][1] = __expf(s[nt][1] - nm1);
            s[nt][2] = __expf(s[nt][2] - nm2);
            s[nt][3] = __expf(s[nt][3] - nm2);
            rs1 += s[nt][0] + s[nt][1];
            rs2 += s[nt][2] + s[nt][3];
        }
        rs1 += __shfl_xor_sync(0xffffffffu, rs1, 1);
        rs1 += __shfl_xor_sync(0xffffffffu, rs1, 2);
        rs2 += __shfl_xor_sync(0xffffffffu, rs2, 1);
        rs2 += __shfl_xor_sync(0xffffffffu, rs2, 2);
        l1 = l1 * f1 + rs1;
        l2 = l2 * f2 + rs2;
#pragma unroll
        for (int nt = 0; nt < 8; nt++) {
            o[nt][0] *= f1; o[nt][1] *= f1;
            o[nt][2] *= f2; o[nt][3] *= f2;
        }

        // write P to per-warp SMEM (tf32)
#pragma unroll
        for (int nt = 0; nt < 8; nt++) {
            uint2 t1 = {f2tf(s[nt][0]), f2tf(s[nt][1])};
            *(uint2*)&pS[pr1][8 * nt + 2 * tg] = t1;
            uint2 t2 = {f2tf(s[nt][2]), f2tf(s[nt][3])};
            *(uint2*)&pS[pr2][8 * nt + 2 * tg] = t2;
        }
        __syncwarp();

        // O += P V
#pragma unroll
        for (int ks = 0; ks < 8; ks++) {
            uint32_t af[4];
            af[0] = pS[pr1][8 * ks + tg];
            af[1] = pS[pr2][8 * ks + tg];
            af[2] = pS[pr1][8 * ks + tg + 4];
            af[3] = pS[pr2][8 * ks + tg + 4];
#pragma unroll
            for (int nt = 0; nt < 8; nt++) {
                uint32_t bf[2];
                bf[0] = vS[8 * ks + tg][8 * nt + g];
                bf[1] = vS[8 * ks + tg + 4][8 * nt + g];
                mma8(o[nt], af, bf);
            }
        }
        __syncthreads();
    }

    // epilogue
    float v1 = 1.0f / l1, v2 = 1.0f / l2;
    float* oB = g_att + (size_t)b * NS * CC + h * DD;
#pragma unroll
    for (int nt = 0; nt < 8; nt++) {
        int d = 8 * nt + 2 * tg;
        float2 a = {o[nt][0] * v1, o[nt][1] * v1};
        float2 bb = {o[nt][2] * v2, o[nt][3] * v2};
        *(float2*)(oB + (size_t)i1 * CC + d) = a;
        *(float2*)(oB + (size_t)i2 * CC + d) = bb;
    }
}

// ---------------- host launcher ----------------
extern "C" void kernel_launch(void* const* d_in, const int* in_sizes, int n_in,
                              void* d_out, int out_size)
{
    (void)in_sizes; (void)n_in; (void)out_size;
    const float* x   = (const float*)d_in[0];
    const float* rel = (const float*)d_in[2];
    const float* Wq  = (const float*)d_in[3];  const float* bq  = (const float*)d_in[4];
    const float* Wk  = (const float*)d_in[5];  const float* bk  = (const float*)d_in[6];
    const float* Wv  = (const float*)d_in[7];  const float* bv  = (const float*)d_in[8];
    const float* Wpk = (const float*)d_in[9];  const float* bpk = (const float*)d_in[10];
    const float* Wpq = (const float*)d_in[11]; const float* bpq = (const float*)d_in[12];
    const float* Wo  = (const float*)d_in[13]; const float* bo  = (const float*)d_in[14];
    float* out = (float*)d_out;

    float *q, *k, *v, *att, *pk, *pq;
    cudaGetSymbolAddress((void**)&q,   g_q);
    cudaGetSymbolAddress((void**)&k,   g_k);
    cudaGetSymbolAddress((void**)&v,   g_v);
    cudaGetSymbolAddress((void**)&att, g_att);
    cudaGetSymbolAddress((void**)&pk,  g_posk);
    cudaGetSymbolAddress((void**)&pq,  g_posq);

    const int QPKP_SMEM = 2 * 128 * 68 * 4;                       // 69632
    const int ATTN_SMEM = (64 * 68 + 64 * 72 + 128 * 68) * 4;     // 70656
    cudaFuncSetAttribute(qpkp_mma, cudaFuncAttributeMaxDynamicSharedMemorySize, QPKP_SMEM);
    cudaFuncSetAttribute(attn_mma, cudaFuncAttributeMaxDynamicSharedMemorySize, ATTN_SMEM);

    dim3 blk(256);
    // q,k,v projections (z-batched)
    proj_mma<<<dim3(CC / 64, (BB * NS) / 128, 3), blk>>>(
        x, BB * NS, Wq, Wk, Wv, bq, bk, bv, q, k, v);
    // pos_k, pos_q projections (z-batched)
    proj_mma<<<dim3(CC / 64, TWOSPAN / 128, 2), blk>>>(
        rel, TWOSPAN, Wpk, Wpq, nullptr, bpk, bpq, nullptr, pk, pq, nullptr);
    // Qp = q @ pos_k^T, Kp = k @ pos_q^T per (b,h)
    qpkp_mma<<<dim3(TWOSPAN / 128, NS / 128, BB * HH * 2), blk, QPKP_SMEM>>>();
    // fused attention
    attn_mma<<<dim3(NS / 128, BB * HH), blk, ATTN_SMEM>>>();
    // output projection
    proj_mma<<<dim3(CC / 64, (BB * NS) / 128, 1), blk>>>(
        att, BB * NS, Wo, nullptr, nullptr, bo, nullptr, nullptr, out, nullptr, nullptr);
}